// round 1
// baseline (speedup 1.0000x reference)
#include <cuda_runtime.h>
#include <math.h>

#define N_NODES 50000
#define N_EDGES 200000

// ---------------- scratch (static device globals, allocation-free) ----------------
__device__ float g_M[256 * 256];        // atom_W1 @ Ws_w
__device__ float g_bcomb[256];          // atom_W1 @ Ws_b + atom_b1
__device__ float g_weff[128];           // Wv^T @ Wcoord
__device__ float g_hid[(size_t)N_NODES * 256];   // silu(xs @ M^T + bcomb)
__device__ float g_ys[(size_t)N_NODES * 256];    // W_tp00 @ s_n
__device__ float g_zv[(size_t)N_NODES * 384];    // zv[n, c*3+i] = sum_d W_tp11[c,d] v[n,d,i]
__device__ float g_tp[N_EDGES];

// ---------------- prep: M = atom_W1 @ Ws_w, bcomb ----------------
__global__ void prep_M(const float* __restrict__ A1, const float* __restrict__ Ws,
                       const float* __restrict__ Wsb, const float* __restrict__ ab1) {
    __shared__ float a1s[256];
    int i = blockIdx.x, j = threadIdx.x;
    a1s[j] = A1[i * 256 + j];
    __syncthreads();
    float acc = 0.f;
#pragma unroll 8
    for (int k = 0; k < 256; k++) acc = fmaf(a1s[k], Ws[k * 256 + j], acc);
    g_M[i * 256 + j] = acc;
    if (j == 0) {
        float b = ab1[i];
        for (int k = 0; k < 256; k++) b = fmaf(a1s[k], Wsb[k], b);
        g_bcomb[i] = b;
    }
}

// ---------------- prep: weff[c] = sum_d Wcoord[d] * Wv[d, c] ----------------
__global__ void prep_weff(const float* __restrict__ Wcoord, const float* __restrict__ Wv) {
    int c = threadIdx.x;
    float acc = 0.f;
#pragma unroll 8
    for (int d = 0; d < 128; d++) acc = fmaf(Wcoord[d], Wv[d * 128 + c], acc);
    g_weff[c] = acc;
}

// ---------------- node GEMM: C(N,512) = xs(N,256) @ [M^T | W_tp00^T] ----------------
// BM=128 nodes, BN=128 cols, BK=8, 256 threads, 8x8 micro-tile (split 4+4 for bank-conflict-free LDS)
#define NG_STR 132
__global__ __launch_bounds__(256) void node_gemm(const float* __restrict__ h,
                                                 const float* __restrict__ Wtp00) {
    __shared__ float As[8 * NG_STR];
    __shared__ float Bs[8 * NG_STR];
    const int t = threadIdx.x;
    const int n0 = blockIdx.x * 128;
    const int by = blockIdx.y;  // 0,1 -> hidden halves; 2,3 -> ys halves
    const float* Bbase = (by < 2) ? (g_M + (size_t)by * 128 * 256)
                                  : (Wtp00 + (size_t)(by - 2) * 128 * 256);
    const int la_n = t >> 1, la_k = (t & 1) * 4;
    const int lb_j = t >> 1, lb_k = (t & 1) * 4;
    const int ty = t >> 4, tx = t & 15;

    float acc[8][8];
#pragma unroll
    for (int m = 0; m < 8; m++)
#pragma unroll
        for (int n = 0; n < 8; n++) acc[m][n] = 0.f;

    for (int k0 = 0; k0 < 256; k0 += 8) {
        int node = n0 + la_n;
        float4 av = make_float4(0.f, 0.f, 0.f, 0.f);
        if (node < N_NODES)
            av = *reinterpret_cast<const float4*>(&h[(size_t)node * 640 + k0 + la_k]);
        As[(la_k + 0) * NG_STR + la_n] = av.x;
        As[(la_k + 1) * NG_STR + la_n] = av.y;
        As[(la_k + 2) * NG_STR + la_n] = av.z;
        As[(la_k + 3) * NG_STR + la_n] = av.w;
        float4 bv = *reinterpret_cast<const float4*>(&Bbase[(size_t)lb_j * 256 + k0 + lb_k]);
        Bs[(lb_k + 0) * NG_STR + lb_j] = bv.x;
        Bs[(lb_k + 1) * NG_STR + lb_j] = bv.y;
        Bs[(lb_k + 2) * NG_STR + lb_j] = bv.z;
        Bs[(lb_k + 3) * NG_STR + lb_j] = bv.w;
        __syncthreads();
#pragma unroll
        for (int kk = 0; kk < 8; kk++) {
            float4 a0 = *reinterpret_cast<const float4*>(&As[kk * NG_STR + ty * 8]);
            float4 a1 = *reinterpret_cast<const float4*>(&As[kk * NG_STR + ty * 8 + 4]);
            float4 b0 = *reinterpret_cast<const float4*>(&Bs[kk * NG_STR + tx * 4]);
            float4 b1 = *reinterpret_cast<const float4*>(&Bs[kk * NG_STR + 64 + tx * 4]);
            float a[8] = {a0.x, a0.y, a0.z, a0.w, a1.x, a1.y, a1.z, a1.w};
            float b[8] = {b0.x, b0.y, b0.z, b0.w, b1.x, b1.y, b1.z, b1.w};
#pragma unroll
            for (int m = 0; m < 8; m++)
#pragma unroll
                for (int n = 0; n < 8; n++) acc[m][n] = fmaf(a[m], b[n], acc[m][n]);
        }
        __syncthreads();
    }

    const bool isHid = (by < 2);
    const int half = (by & 1) * 128;
#pragma unroll
    for (int m = 0; m < 8; m++) {
        int node = n0 + ty * 8 + m;
        if (node >= N_NODES) continue;
#pragma unroll
        for (int n = 0; n < 8; n++) {
            int jl = (n < 4) ? (tx * 4 + n) : (64 + tx * 4 + (n - 4));
            int j = half + jl;
            float c = acc[m][n];
            if (isHid) {
                float x = c + g_bcomb[j];
                g_hid[(size_t)node * 256 + j] = x / (1.f + __expf(-x));
            } else {
                g_ys[(size_t)node * 256 + j] = c;
            }
        }
    }
}

// ---------------- zv + r0 kernel ----------------
// zv[n, c*3+i] = sum_d W_tp11[c,d] * v[n, 3d+i] ; r0[n,i] = sum_c v[n,3c+i]*weff[c]
#define ZV_NODES 16
#define ZV_VST 388
#define ZV_WST 129
__global__ __launch_bounds__(192) void zv_kernel(const float* __restrict__ h,
                                                 const float* __restrict__ Wtp11,
                                                 float* __restrict__ out_r0) {
    extern __shared__ float sm[];
    float* Wsm = sm;                     // 128 * 129
    float* vs = sm + 128 * ZV_WST;       // 16 * 388
    const int t = threadIdx.x;
    const int n0 = blockIdx.x * ZV_NODES;

    for (int idx = t; idx < 128 * 128; idx += 192) {
        int c = idx >> 7, d = idx & 127;
        Wsm[c * ZV_WST + d] = Wtp11[idx];
    }
    for (int q = t; q < ZV_NODES * 96; q += 192) {
        int n = q / 96, k4 = (q % 96) * 4;
        float4 v = *reinterpret_cast<const float4*>(&h[(size_t)(n0 + n) * 640 + 256 + k4]);
        *reinterpret_cast<float4*>(&vs[n * ZV_VST + k4]) = v;
    }
    __syncthreads();

    if (t < 48) {
        int n = t / 3, i = t % 3;
        float acc = 0.f;
#pragma unroll 8
        for (int c = 0; c < 128; c++) acc = fmaf(vs[n * ZV_VST + 3 * c + i], g_weff[c], acc);
        out_r0[(size_t)(n0 + n) * 3 + i] = acc;
    }

    const int i = t % 3;
    const int c0 = (t / 3) * 2;
    float acc0[ZV_NODES], acc1[ZV_NODES];
#pragma unroll
    for (int n = 0; n < ZV_NODES; n++) { acc0[n] = 0.f; acc1[n] = 0.f; }
#pragma unroll 4
    for (int d = 0; d < 128; d++) {
        float w0 = Wsm[c0 * ZV_WST + d];
        float w1 = Wsm[(c0 + 1) * ZV_WST + d];
#pragma unroll
        for (int n = 0; n < ZV_NODES; n++) {
            float vv = vs[n * ZV_VST + 3 * d + i];
            acc0[n] = fmaf(w0, vv, acc0[n]);
            acc1[n] = fmaf(w1, vv, acc1[n]);
        }
    }
#pragma unroll
    for (int n = 0; n < ZV_NODES; n++) {
        g_zv[(size_t)(n0 + n) * 384 + c0 * 3 + i] = acc0[n];
        g_zv[(size_t)(n0 + n) * 384 + (c0 + 1) * 3 + i] = acc1[n];
    }
}

// ---------------- atom logits: (16 nodes/block) hid @ A2^T + b2 ----------------
__global__ __launch_bounds__(256) void atom_kernel(float* __restrict__ out,
                                                   const float* __restrict__ A2,
                                                   const float* __restrict__ b2) {
    __shared__ float hs[16 * 260];
    __shared__ float a2s[16 * 257];
    __shared__ float b2s[16];
    const int t = threadIdx.x;
    const int n0 = blockIdx.x * 16;
    for (int q = t; q < 16 * 64; q += 256) {
        int n = q >> 6, k4 = (q & 63) * 4;
        *reinterpret_cast<float4*>(&hs[n * 260 + k4]) =
            *reinterpret_cast<const float4*>(&g_hid[(size_t)(n0 + n) * 256 + k4]);
    }
    for (int idx = t; idx < 4096; idx += 256) {
        int j = idx >> 8, k = idx & 255;
        a2s[j * 257 + k] = A2[idx];
    }
    if (t < 16) b2s[t] = b2[t];
    __syncthreads();
    const int n = t >> 4, j = t & 15;
    float acc = 0.f;
#pragma unroll 8
    for (int k = 0; k < 256; k++) acc = fmaf(hs[n * 260 + k], a2s[j * 257 + k], acc);
    out[(size_t)(n0 + n) * 16 + j] = acc + b2s[j];
}

// ---------------- tp kernel: warp per edge ----------------
__global__ __launch_bounds__(256) void tp_kernel(const float* __restrict__ h,
                                                 const int* __restrict__ ei) {
    const int w = threadIdx.x >> 5, l = threadIdx.x & 31;
    const int e = blockIdx.x * 8 + w;
    const int row = ei[e];
    const int col = ei[N_EDGES + e];
    const float* hr = h + (size_t)row * 640;
    const float* ysc = g_ys + (size_t)col * 256;
    const float* zvc = g_zv + (size_t)col * 384;
    float ss = 0.f, vv = 0.f;
#pragma unroll
    for (int q = 0; q < 8; q++) ss = fmaf(hr[l + 32 * q], ysc[l + 32 * q], ss);
#pragma unroll
    for (int q = 0; q < 12; q++) vv = fmaf(hr[256 + l + 32 * q], zvc[l + 32 * q], vv);
    float val = ss + vv * 0.57735026919f;  // 1/sqrt(3)
#pragma unroll
    for (int off = 16; off; off >>= 1) val += __shfl_xor_sync(0xffffffffu, val, off);
    if (l == 0) g_tp[e] = val * (1.0f / sqrtf(81920.0f));  // 1/sqrt(FAN_TP)
}

// ---------------- bond MLP (fused, 32 edges/block) ----------------
// hid = silu([tp|e_final] @ W1^T + b1); logits = hid @ W2^T + b2
__global__ __launch_bounds__(256) void bond_kernel(float* __restrict__ out,
                                                   const float* __restrict__ ef,
                                                   const float* __restrict__ W1,
                                                   const float* __restrict__ b1,
                                                   const float* __restrict__ W2,
                                                   const float* __restrict__ b2) {
    extern __shared__ float sm[];
    float* W1s = sm;                    // 65*256 (k-major, transposed)
    float* ins = W1s + 65 * 256;        // 65*32
    float* hid = ins + 65 * 32;         // 256*33
    float* W2s = hid + 256 * 33;        // 5*257
    float* b1s = W2s + 5 * 257;         // 256
    float* b2s = b1s + 256;             // 8
    const int t = threadIdx.x;
    const int e0 = blockIdx.x * 32;

    for (int idx = t; idx < 65 * 256; idx += 256) {
        int o = idx / 65, k = idx % 65;
        W1s[k * 256 + o] = W1[idx];
    }
    for (int idx = t; idx < 65 * 32; idx += 256) {
        int k = idx >> 5, e = idx & 31;
        ins[idx] = (k == 0) ? g_tp[e0 + e] : ef[(size_t)(e0 + e) * 64 + (k - 1)];
    }
    b1s[t] = b1[t];
    for (int idx = t; idx < 5 * 256; idx += 256) {
        int j = idx >> 8, o = idx & 255;
        W2s[j * 257 + o] = W2[idx];
    }
    if (t < 5) b2s[t] = b2[t];
    __syncthreads();

    const int m = t & 31;       // 32 o-groups (split 4 + 4 @ +128)
    const int el = (t >> 5) * 4;  // 8 edge-groups of 4
    float acc[8][4];
#pragma unroll
    for (int a = 0; a < 8; a++)
#pragma unroll
        for (int bq = 0; bq < 4; bq++) acc[a][bq] = 0.f;
#pragma unroll 5
    for (int k = 0; k < 65; k++) {
        float4 w0 = *reinterpret_cast<const float4*>(&W1s[k * 256 + m * 4]);
        float4 w1 = *reinterpret_cast<const float4*>(&W1s[k * 256 + 128 + m * 4]);
        float4 iv = *reinterpret_cast<const float4*>(&ins[k * 32 + el]);
        float wv[8] = {w0.x, w0.y, w0.z, w0.w, w1.x, w1.y, w1.z, w1.w};
        float ivv[4] = {iv.x, iv.y, iv.z, iv.w};
#pragma unroll
        for (int a = 0; a < 8; a++)
#pragma unroll
            for (int bq = 0; bq < 4; bq++) acc[a][bq] = fmaf(wv[a], ivv[bq], acc[a][bq]);
    }
#pragma unroll
    for (int a = 0; a < 8; a++) {
        int o = (a < 4) ? (m * 4 + a) : (128 + m * 4 + (a - 4));
        float bb = b1s[o];
#pragma unroll
        for (int bq = 0; bq < 4; bq++) {
            float x = acc[a][bq] + bb;
            hid[o * 33 + (el + bq)] = x / (1.f + __expf(-x));
        }
    }
    __syncthreads();

    if (t < 160) {
        int e = t / 5, j = t % 5;
        float acc2 = b2s[j];
#pragma unroll 8
        for (int o = 0; o < 256; o++) acc2 = fmaf(hid[o * 33 + e], W2s[j * 257 + o], acc2);
        out[(size_t)(e0 + e) * 5 + j] = acc2;
    }
}

// ---------------- launch ----------------
extern "C" void kernel_launch(void* const* d_in, const int* in_sizes, int n_in,
                              void* d_out, int out_size) {
    const float* h_final = (const float*)d_in[0];
    const float* e_final = (const float*)d_in[1];
    // d_in[2], d_in[3]: node/edge masks — all-ones by construction, unused
    const int* edge_index = (const int*)d_in[4];
    const float* Ws_w = (const float*)d_in[5];
    const float* Ws_b = (const float*)d_in[6];
    const float* Wv = (const float*)d_in[7];
    const float* Wcoord = (const float*)d_in[8];
    const float* W_tp00 = (const float*)d_in[9];
    const float* W_tp11 = (const float*)d_in[10];
    const float* atom_W1 = (const float*)d_in[11];
    const float* atom_b1 = (const float*)d_in[12];
    const float* atom_W2 = (const float*)d_in[13];
    const float* atom_b2 = (const float*)d_in[14];
    const float* bond_W1 = (const float*)d_in[15];
    const float* bond_b1 = (const float*)d_in[16];
    const float* bond_W2 = (const float*)d_in[17];
    const float* bond_b2 = (const float*)d_in[18];

    float* out = (float*)d_out;
    float* out_atom = out;
    float* out_r0 = out + (size_t)N_NODES * 16;
    float* out_bond = out + (size_t)N_NODES * 16 + (size_t)N_NODES * 3;

    const int ZV_SMEM = (128 * ZV_WST + ZV_NODES * ZV_VST) * 4;          // 90880 B
    const int BD_SMEM = (65 * 256 + 65 * 32 + 256 * 33 + 5 * 257 + 256 + 8) * 4;  // 114868 B
    cudaFuncSetAttribute(zv_kernel, cudaFuncAttributeMaxDynamicSharedMemorySize, ZV_SMEM);
    cudaFuncSetAttribute(bond_kernel, cudaFuncAttributeMaxDynamicSharedMemorySize, BD_SMEM);

    prep_M<<<256, 256>>>(atom_W1, Ws_w, Ws_b, atom_b1);
    prep_weff<<<1, 128>>>(Wcoord, Wv);
    node_gemm<<<dim3((N_NODES + 127) / 128, 4), 256>>>(h_final, W_tp00);
    zv_kernel<<<N_NODES / ZV_NODES, 192, ZV_SMEM>>>(h_final, W_tp11, out_r0);
    atom_kernel<<<N_NODES / 16, 256>>>(out_atom, atom_W2, atom_b2);
    tp_kernel<<<N_EDGES / 8, 256>>>(h_final, edge_index);
    bond_kernel<<<N_EDGES / 32, 256, BD_SMEM>>>(out_bond, e_final, bond_W1, bond_b1,
                                                bond_W2, bond_b2);
}

// round 2
// speedup vs baseline: 1.3854x; 1.3854x over previous
#include <cuda_runtime.h>
#include <math.h>

#define N_NODES 50000
#define N_EDGES 200000

typedef unsigned long long u64;

// ---- packed fp32x2 helpers (FFMA2 path; ptxas never emits these from C++) ----
__device__ __forceinline__ u64 pk2(float x, float y) {
    u64 r; asm("mov.b64 %0,{%1,%2};" : "=l"(r) : "f"(x), "f"(y)); return r;
}
__device__ __forceinline__ void fma2(u64& d, u64 a, u64 b) {
    asm("fma.rn.f32x2 %0,%1,%2,%0;" : "+l"(d) : "l"(a), "l"(b));
}
__device__ __forceinline__ float2 up2(u64 v) {
    float2 r; asm("mov.b64 {%0,%1},%2;" : "=f"(r.x), "=f"(r.y) : "l"(v)); return r;
}

// ---------------- scratch ----------------
__device__ float g_M[256 * 256];
__device__ float g_bcomb[256];
__device__ float g_weff[128];
__device__ float g_hid[(size_t)N_NODES * 256];
__device__ float g_ys[(size_t)N_NODES * 256];
__device__ float g_zv[(size_t)N_NODES * 384];
__device__ float g_tp[N_EDGES];

// ---------------- prep ----------------
__global__ void prep_M(const float* __restrict__ A1, const float* __restrict__ Ws,
                       const float* __restrict__ Wsb, const float* __restrict__ ab1) {
    __shared__ float a1s[256];
    int i = blockIdx.x, j = threadIdx.x;
    a1s[j] = A1[i * 256 + j];
    __syncthreads();
    float acc = 0.f;
#pragma unroll 8
    for (int k = 0; k < 256; k++) acc = fmaf(a1s[k], Ws[k * 256 + j], acc);
    g_M[i * 256 + j] = acc;
    if (j == 0) {
        float b = ab1[i];
        for (int k = 0; k < 256; k++) b = fmaf(a1s[k], Wsb[k], b);
        g_bcomb[i] = b;
    }
}

__global__ void prep_weff(const float* __restrict__ Wcoord, const float* __restrict__ Wv) {
    int c = threadIdx.x;
    float acc = 0.f;
#pragma unroll 8
    for (int d = 0; d < 128; d++) acc = fmaf(Wcoord[d], Wv[d * 128 + c], acc);
    g_weff[c] = acc;
}

// ---------------- node GEMM: (N,256) @ (256,512), BK=16, reg-prefetch, f32x2 ----------------
#define NG_STR 132
__global__ __launch_bounds__(256) void node_gemm(const float* __restrict__ h,
                                                 const float* __restrict__ Wtp00) {
    __shared__ float As[16 * NG_STR];
    __shared__ float Bs[16 * NG_STR];
    const int t = threadIdx.x;
    const int n0 = blockIdx.x * 128;
    const int by = blockIdx.y;
    const float* Bbase = (by < 2) ? (g_M + (size_t)by * 128 * 256)
                                  : (Wtp00 + (size_t)(by - 2) * 128 * 256);
    const int lr = t >> 1;
    const int lk = (t & 1) * 8;
    const int ty = t >> 4, tx = t & 15;
    const int anode = n0 + lr;
    const bool aval = anode < N_NODES;
    const float* Aptr = h + (size_t)anode * 640 + lk;
    const float* Bptr = Bbase + (size_t)lr * 256 + lk;

    u64 acc[8][4];
#pragma unroll
    for (int m = 0; m < 8; m++)
#pragma unroll
        for (int q = 0; q < 4; q++) acc[m][q] = 0ull;

    float4 pa0, pa1, pb0, pb1;
    const float4 z4 = make_float4(0.f, 0.f, 0.f, 0.f);
    pa0 = aval ? *(const float4*)(Aptr + 0) : z4;
    pa1 = aval ? *(const float4*)(Aptr + 4) : z4;
    pb0 = *(const float4*)(Bptr + 0);
    pb1 = *(const float4*)(Bptr + 4);

    const u64* B64 = (const u64*)Bs;
    for (int k0 = 0; k0 < 256; k0 += 16) {
        As[(lk + 0) * NG_STR + lr] = pa0.x;
        As[(lk + 1) * NG_STR + lr] = pa0.y;
        As[(lk + 2) * NG_STR + lr] = pa0.z;
        As[(lk + 3) * NG_STR + lr] = pa0.w;
        As[(lk + 4) * NG_STR + lr] = pa1.x;
        As[(lk + 5) * NG_STR + lr] = pa1.y;
        As[(lk + 6) * NG_STR + lr] = pa1.z;
        As[(lk + 7) * NG_STR + lr] = pa1.w;
        Bs[(lk + 0) * NG_STR + lr] = pb0.x;
        Bs[(lk + 1) * NG_STR + lr] = pb0.y;
        Bs[(lk + 2) * NG_STR + lr] = pb0.z;
        Bs[(lk + 3) * NG_STR + lr] = pb0.w;
        Bs[(lk + 4) * NG_STR + lr] = pb1.x;
        Bs[(lk + 5) * NG_STR + lr] = pb1.y;
        Bs[(lk + 6) * NG_STR + lr] = pb1.z;
        Bs[(lk + 7) * NG_STR + lr] = pb1.w;
        __syncthreads();
        if (k0 + 16 < 256) {
            pa0 = aval ? *(const float4*)(Aptr + k0 + 16) : z4;
            pa1 = aval ? *(const float4*)(Aptr + k0 + 20) : z4;
            pb0 = *(const float4*)(Bptr + k0 + 16);
            pb1 = *(const float4*)(Bptr + k0 + 20);
        }
#pragma unroll
        for (int kk = 0; kk < 16; kk++) {
            float4 a0 = *(const float4*)&As[kk * NG_STR + ty * 8];
            float4 a1 = *(const float4*)&As[kk * NG_STR + ty * 8 + 4];
            u64 b0 = B64[kk * 66 + tx * 2];
            u64 b1 = B64[kk * 66 + tx * 2 + 1];
            u64 b2 = B64[kk * 66 + 32 + tx * 2];
            u64 b3 = B64[kk * 66 + 33 + tx * 2];
            float av[8] = {a0.x, a0.y, a0.z, a0.w, a1.x, a1.y, a1.z, a1.w};
#pragma unroll
            for (int m = 0; m < 8; m++) {
                u64 aa = pk2(av[m], av[m]);
                fma2(acc[m][0], aa, b0);
                fma2(acc[m][1], aa, b1);
                fma2(acc[m][2], aa, b2);
                fma2(acc[m][3], aa, b3);
            }
        }
        __syncthreads();
    }

    const bool isHid = (by < 2);
    const int half = (by & 1) * 128;
#pragma unroll
    for (int m = 0; m < 8; m++) {
        int node = n0 + ty * 8 + m;
        if (node >= N_NODES) continue;
#pragma unroll
        for (int q = 0; q < 4; q++) {
            float2 v = up2(acc[m][q]);
            int jl = (q < 2) ? (tx * 4 + q * 2) : (64 + tx * 4 + (q - 2) * 2);
            int j = half + jl;
            if (isHid) {
                float x0 = v.x + g_bcomb[j];
                float x1 = v.y + g_bcomb[j + 1];
                g_hid[(size_t)node * 256 + j]     = x0 / (1.f + __expf(-x0));
                g_hid[(size_t)node * 256 + j + 1] = x1 / (1.f + __expf(-x1));
            } else {
                g_ys[(size_t)node * 256 + j]     = v.x;
                g_ys[(size_t)node * 256 + j + 1] = v.y;
            }
        }
    }
}

// ---------------- zv + r0: 32 nodes/block (96 rows x 128 cols), K-chunked W, f32x2 ----------------
#define ZVN 32
#define ZV_VST 388
#define ZV_BST 132
__global__ __launch_bounds__(256) void zv_kernel(const float* __restrict__ h,
                                                 const float* __restrict__ Wtp11,
                                                 float* __restrict__ out_r0) {
    extern __shared__ float sm[];
    float* vs = sm;                        // 32*388
    float* Bs = sm + ZVN * ZV_VST;         // 32*132 (transposed chunk: [dd][c])
    float* weffs = Bs + 32 * ZV_BST;       // 128
    const int t = threadIdx.x;
    const int n0 = blockIdx.x * ZVN;

#pragma unroll
    for (int q = 0; q < 12; q++) {
        int fidx = t + 256 * q;
        int n = fidx / 96, k4 = (fidx % 96) * 4;
        float4 v = (n0 + n < N_NODES)
                       ? *(const float4*)&h[(size_t)(n0 + n) * 640 + 256 + k4]
                       : make_float4(0.f, 0.f, 0.f, 0.f);
        *(float4*)&vs[n * ZV_VST + k4] = v;
    }
    if (t < 128) weffs[t] = g_weff[t];
    __syncthreads();

    if (t < 96) {
        int n = t / 3, i = t % 3;
        if (n0 + n < N_NODES) {
            float acc = 0.f;
#pragma unroll 8
            for (int c = 0; c < 128; c++) acc = fmaf(vs[n * ZV_VST + 3 * c + i], weffs[c], acc);
            out_r0[(size_t)(n0 + n) * 3 + i] = acc;
        }
    }

    const int ty = t >> 4, tx = t & 15;
    int voff[6];
#pragma unroll
    for (int j = 0; j < 6; j++) {
        int r = ty * 6 + j;
        voff[j] = (r / 3) * ZV_VST + (r % 3);
    }
    u64 acc[6][4];
#pragma unroll
    for (int j = 0; j < 6; j++)
#pragma unroll
        for (int q = 0; q < 4; q++) acc[j][q] = 0ull;

    const u64* B64 = (const u64*)Bs;
    for (int ch = 0; ch < 4; ch++) {
        if (ch) __syncthreads();
        int d0 = ch * 32;
#pragma unroll
        for (int q = 0; q < 4; q++) {
            int fidx = t + 256 * q;        // 1024 float4s total
            int c = fidx >> 3, d4 = (fidx & 7) * 4;
            float4 w = *(const float4*)&Wtp11[c * 128 + d0 + d4];
            Bs[(d4 + 0) * ZV_BST + c] = w.x;
            Bs[(d4 + 1) * ZV_BST + c] = w.y;
            Bs[(d4 + 2) * ZV_BST + c] = w.z;
            Bs[(d4 + 3) * ZV_BST + c] = w.w;
        }
        __syncthreads();
#pragma unroll 4
        for (int dd = 0; dd < 32; dd++) {
            int d3 = (d0 + dd) * 3;
            u64 b0 = B64[dd * 66 + tx * 2];
            u64 b1 = B64[dd * 66 + tx * 2 + 1];
            u64 b2 = B64[dd * 66 + 32 + tx * 2];
            u64 b3 = B64[dd * 66 + 33 + tx * 2];
#pragma unroll
            for (int j = 0; j < 6; j++) {
                float a = vs[voff[j] + d3];
                u64 aa = pk2(a, a);
                fma2(acc[j][0], aa, b0);
                fma2(acc[j][1], aa, b1);
                fma2(acc[j][2], aa, b2);
                fma2(acc[j][3], aa, b3);
            }
        }
    }

#pragma unroll
    for (int j = 0; j < 6; j++) {
        int r = ty * 6 + j;
        int n = r / 3, i = r % 3;
        if (n0 + n >= N_NODES) continue;
        float* dst = &g_zv[(size_t)(n0 + n) * 384 + i];
#pragma unroll
        for (int q = 0; q < 4; q++) {
            float2 v = up2(acc[j][q]);
            int c0 = (q < 2) ? (tx * 4 + q * 2) : (64 + tx * 4 + (q - 2) * 2);
            dst[c0 * 3] = v.x;
            dst[(c0 + 1) * 3] = v.y;
        }
    }
}

// ---------------- atom logits ----------------
__global__ __launch_bounds__(256) void atom_kernel(float* __restrict__ out,
                                                   const float* __restrict__ A2,
                                                   const float* __restrict__ b2) {
    __shared__ float hs[16 * 260];
    __shared__ float a2s[16 * 257];
    __shared__ float b2s[16];
    const int t = threadIdx.x;
    const int n0 = blockIdx.x * 16;
    for (int q = t; q < 16 * 64; q += 256) {
        int n = q >> 6, k4 = (q & 63) * 4;
        *(float4*)&hs[n * 260 + k4] = *(const float4*)&g_hid[(size_t)(n0 + n) * 256 + k4];
    }
    for (int idx = t; idx < 4096; idx += 256) {
        int j = idx >> 8, k = idx & 255;
        a2s[j * 257 + k] = A2[idx];
    }
    if (t < 16) b2s[t] = b2[t];
    __syncthreads();
    const int n = t >> 4, j = t & 15;
    float acc = 0.f;
#pragma unroll 8
    for (int k = 0; k < 256; k++) acc = fmaf(hs[n * 260 + k], a2s[j * 257 + k], acc);
    out[(size_t)(n0 + n) * 16 + j] = acc + b2s[j];
}

// ---------------- tp: warp/edge, float4 gathers ----------------
__global__ __launch_bounds__(256) void tp_kernel(const float* __restrict__ h,
                                                 const int* __restrict__ ei) {
    const int w = threadIdx.x >> 5, l = threadIdx.x & 31;
    const int e = blockIdx.x * 8 + w;
    const int row = ei[e];
    const int col = ei[N_EDGES + e];
    const float4* hr4 = (const float4*)(h + (size_t)row * 640);
    const float4* ys4 = (const float4*)(g_ys + (size_t)col * 256);
    const float4* zv4 = (const float4*)(g_zv + (size_t)col * 384);
    const float4* hv4 = hr4 + 64;
    float ss = 0.f, vv = 0.f;
#pragma unroll
    for (int q = 0; q < 2; q++) {
        float4 x = hr4[l + 32 * q], y = ys4[l + 32 * q];
        ss = fmaf(x.x, y.x, ss); ss = fmaf(x.y, y.y, ss);
        ss = fmaf(x.z, y.z, ss); ss = fmaf(x.w, y.w, ss);
    }
#pragma unroll
    for (int q = 0; q < 3; q++) {
        float4 x = hv4[l + 32 * q], z = zv4[l + 32 * q];
        vv = fmaf(x.x, z.x, vv); vv = fmaf(x.y, z.y, vv);
        vv = fmaf(x.z, z.z, vv); vv = fmaf(x.w, z.w, vv);
    }
    float val = fmaf(vv, 0.57735026919f, ss);
#pragma unroll
    for (int off = 16; off; off >>= 1) val += __shfl_xor_sync(0xffffffffu, val, off);
    if (l == 0) g_tp[e] = val * (1.0f / sqrtf(81920.0f));
}

// ---------------- bond MLP: 64 edges/block, 512 threads, f32x2 + warp-reduce stage2 ----------------
__global__ __launch_bounds__(512) void bond_kernel(float* __restrict__ out,
                                                   const float* __restrict__ ef,
                                                   const float* __restrict__ W1,
                                                   const float* __restrict__ b1,
                                                   const float* __restrict__ W2,
                                                   const float* __restrict__ b2) {
    extern __shared__ float sm[];
    float* W1s = sm;                 // [k][256] (k-major)
    float* ins = W1s + 65 * 256;     // [k][64]
    float* W2s = ins + 65 * 64;      // [j*257+o]
    float* b1s = W2s + 5 * 257;      // 256
    float* b2s = b1s + 256;          // 8
    const int t = threadIdx.x;
    const int e0 = blockIdx.x * 64;

    for (int idx = t; idx < 65 * 256; idx += 512) {
        int o = idx / 65, k = idx % 65;
        W1s[k * 256 + o] = W1[idx];
    }
    if (t < 64) ins[t] = g_tp[e0 + t];
#pragma unroll
    for (int q = 0; q < 2; q++) {
        int f = t + 512 * q;          // 1024 float4s over ef block [64e][64k]
        int e = f >> 4, k4 = (f & 15) * 4;
        float4 v = *(const float4*)&ef[(size_t)(e0 + e) * 64 + k4];
        ins[(k4 + 1) * 64 + e] = v.x;
        ins[(k4 + 2) * 64 + e] = v.y;
        ins[(k4 + 3) * 64 + e] = v.z;
        ins[(k4 + 4) * 64 + e] = v.w;
    }
    if (t < 256) b1s[t] = b1[t];
    for (int idx = t; idx < 1280; idx += 512) {
        int j = idx >> 8, o = idx & 255;
        W2s[j * 257 + o] = W2[idx];
    }
    if (t < 5) b2s[t] = b2[t];
    __syncthreads();

    const int m = t & 31;
    const int el = (t >> 5) * 4;
    u64 acc[4][4];
#pragma unroll
    for (int p = 0; p < 4; p++)
#pragma unroll
        for (int b = 0; b < 4; b++) acc[p][b] = 0ull;

    const u64* W164 = (const u64*)W1s;
#pragma unroll 5
    for (int k = 0; k < 65; k++) {
        u64 w0 = W164[k * 128 + m * 2];
        u64 w1 = W164[k * 128 + m * 2 + 1];
        u64 w2 = W164[k * 128 + 64 + m * 2];
        u64 w3 = W164[k * 128 + 65 + m * 2];
        float4 iv = *(const float4*)&ins[k * 64 + el];
        u64 i0 = pk2(iv.x, iv.x), i1 = pk2(iv.y, iv.y);
        u64 i2 = pk2(iv.z, iv.z), i3 = pk2(iv.w, iv.w);
        fma2(acc[0][0], i0, w0); fma2(acc[0][1], i1, w0);
        fma2(acc[0][2], i2, w0); fma2(acc[0][3], i3, w0);
        fma2(acc[1][0], i0, w1); fma2(acc[1][1], i1, w1);
        fma2(acc[1][2], i2, w1); fma2(acc[1][3], i3, w1);
        fma2(acc[2][0], i0, w2); fma2(acc[2][1], i1, w2);
        fma2(acc[2][2], i2, w2); fma2(acc[2][3], i3, w2);
        fma2(acc[3][0], i0, w3); fma2(acc[3][1], i1, w3);
        fma2(acc[3][2], i2, w3); fma2(acc[3][3], i3, w3);
    }

    // silu(acc + b1) -> hsl[a][b]  (a: 8 o-values of this thread; b: 4 edges)
    float hsl[8][4];
#pragma unroll
    for (int p = 0; p < 4; p++) {
        int ob = (p < 2) ? (m * 4 + p * 2) : (128 + m * 4 + (p - 2) * 2);
        float bb0 = b1s[ob], bb1 = b1s[ob + 1];
#pragma unroll
        for (int b = 0; b < 4; b++) {
            float2 v = up2(acc[p][b]);
            float x0 = v.x + bb0, x1 = v.y + bb1;
            hsl[p * 2 + 0][b] = x0 / (1.f + __expf(-x0));
            hsl[p * 2 + 1][b] = x1 / (1.f + __expf(-x1));
        }
    }

    // stage 2 partials + warp butterfly reduce
    float p5[5][4];
#pragma unroll
    for (int j = 0; j < 5; j++) {
        float w2v[8];
#pragma unroll
        for (int a = 0; a < 8; a++) {
            int o = (a < 4) ? (m * 4 + a) : (128 + m * 4 + (a - 4));
            w2v[a] = W2s[j * 257 + o];
        }
#pragma unroll
        for (int b = 0; b < 4; b++) {
            float s = 0.f;
#pragma unroll
            for (int a = 0; a < 8; a++) s = fmaf(hsl[a][b], w2v[a], s);
            p5[j][b] = s;
        }
    }
#pragma unroll
    for (int j = 0; j < 5; j++)
#pragma unroll
        for (int b = 0; b < 4; b++) {
            float v = p5[j][b];
#pragma unroll
            for (int off = 16; off; off >>= 1) v += __shfl_xor_sync(0xffffffffu, v, off);
            p5[j][b] = v;
        }
    if (m < 20) {
        int b = m / 5, j = m % 5;
        float val = 0.f;
#pragma unroll
        for (int jj = 0; jj < 5; jj++)
#pragma unroll
            for (int bb = 0; bb < 4; bb++)
                if (jj == j && bb == b) val = p5[jj][bb];
        out[(size_t)(e0 + el + b) * 5 + j] = val + b2s[j];
    }
}

// ---------------- launch ----------------
extern "C" void kernel_launch(void* const* d_in, const int* in_sizes, int n_in,
                              void* d_out, int out_size) {
    const float* h_final = (const float*)d_in[0];
    const float* e_final = (const float*)d_in[1];
    const int* edge_index = (const int*)d_in[4];
    const float* Ws_w = (const float*)d_in[5];
    const float* Ws_b = (const float*)d_in[6];
    const float* Wv = (const float*)d_in[7];
    const float* Wcoord = (const float*)d_in[8];
    const float* W_tp00 = (const float*)d_in[9];
    const float* W_tp11 = (const float*)d_in[10];
    const float* atom_W1 = (const float*)d_in[11];
    const float* atom_b1 = (const float*)d_in[12];
    const float* atom_W2 = (const float*)d_in[13];
    const float* atom_b2 = (const float*)d_in[14];
    const float* bond_W1 = (const float*)d_in[15];
    const float* bond_b1 = (const float*)d_in[16];
    const float* bond_W2 = (const float*)d_in[17];
    const float* bond_b2 = (const float*)d_in[18];

    float* out = (float*)d_out;
    float* out_atom = out;
    float* out_r0 = out + (size_t)N_NODES * 16;
    float* out_bond = out + (size_t)N_NODES * 16 + (size_t)N_NODES * 3;

    const int ZV_SMEM = (ZVN * ZV_VST + 32 * ZV_BST + 128) * 4;
    const int BD_SMEM = (65 * 256 + 65 * 64 + 5 * 257 + 256 + 8) * 4;
    cudaFuncSetAttribute(zv_kernel, cudaFuncAttributeMaxDynamicSharedMemorySize, ZV_SMEM);
    cudaFuncSetAttribute(bond_kernel, cudaFuncAttributeMaxDynamicSharedMemorySize, BD_SMEM);

    prep_M<<<256, 256>>>(atom_W1, Ws_w, Ws_b, atom_b1);
    prep_weff<<<1, 128>>>(Wcoord, Wv);
    node_gemm<<<dim3((N_NODES + 127) / 128, 4), 256>>>(h_final, W_tp00);
    zv_kernel<<<(N_NODES + ZVN - 1) / ZVN, 256, ZV_SMEM>>>(h_final, W_tp11, out_r0);
    atom_kernel<<<N_NODES / 16, 256>>>(out_atom, atom_W2, atom_b2);
    tp_kernel<<<N_EDGES / 8, 256>>>(h_final, edge_index);
    bond_kernel<<<N_EDGES / 64, 512, BD_SMEM>>>(out_bond, e_final, bond_W1, bond_b1,
                                                bond_W2, bond_b2);
}